// round 1
// baseline (speedup 1.0000x reference)
#include <cuda_runtime.h>
#include <math.h>

// Problem constants
#define BB   4
#define MM   8
#define NPP  4096
#define HH   256
#define FDD  512
#define SS   128

#define NPTS   (BB * NPP)        // 16384 point rows
#define NVIEWS (BB * MM * NPP)   // 131072 view rows

// ---------------------------------------------------------------------------
// Scratch (static device globals; no allocation allowed)
// ---------------------------------------------------------------------------
static __device__ float g_pp[NPTS * HH];        // relu(LN(PF@p_W))
static __device__ float g_ppa[NPTS * HH];       // pp @ a1_W_top + a1_b
static __device__ float g_attn[NVIEWS];         // sigmoid attention, [B,M,NP] order
static __device__ float g_segcnt[BB * SS];
static __device__ float g_sega[BB * SS * MM];
static __device__ float g_segf[BB * SS * HH];
static __device__ float g_weighted[NPTS * HH];  // softmax-weighted view feats
static __device__ float g_wvp[NPTS * HH];       // relu(LN(weighted@v_W))

// ---------------------------------------------------------------------------
// Generic fused row GEMM (+ optional concat-K input, + optional LN(+ReLU))
//   out[r, n] = act( LN_n( bias[n] + sum_k xs[r,k] * W[k*N+n] ) )
// One block computes ROWS full rows so LayerNorm is block-local.
// ---------------------------------------------------------------------------
template <int ROWS, int K, int N, bool DOLN, bool DORELU>
__global__ void __launch_bounds__(N)
rowgemm(const float* __restrict__ X, const float* __restrict__ X2,
        const float* __restrict__ W, const float* __restrict__ bias,
        const float* __restrict__ gamma, const float* __restrict__ beta,
        float* __restrict__ out)
{
    __shared__ float xs[ROWS][K];
    __shared__ float ob[DOLN ? ROWS : 1][N];

    const int tid = threadIdx.x;
    const size_t rowbase = (size_t)blockIdx.x * ROWS;
    constexpr int K4 = K / 4;
    constexpr int TOT4 = ROWS * K4;

    if (X2 == nullptr) {
        for (int idx = tid; idx < TOT4; idx += N) {
            int r = idx / K4, k4 = idx - r * K4;
            ((float4*)xs[r])[k4] =
                ((const float4*)(X + (rowbase + r) * K))[k4];
        }
    } else {
        constexpr int KH4 = K4 / 2;   // concat: first half from X, second from X2
        for (int idx = tid; idx < TOT4; idx += N) {
            int r = idx / K4, k4 = idx - r * K4;
            float4 v;
            if (k4 < KH4) v = ((const float4*)(X  + (rowbase + r) * (K / 2)))[k4];
            else          v = ((const float4*)(X2 + (rowbase + r) * (K / 2)))[k4 - KH4];
            ((float4*)xs[r])[k4] = v;
        }
    }
    __syncthreads();

    float acc[ROWS];
    {
        float bv = bias[tid];
#pragma unroll
        for (int r = 0; r < ROWS; r++) acc[r] = bv;
    }

    const float* wp = W + tid;
    for (int k = 0; k < K; k += 4) {
        float w0 = wp[(k + 0) * N];
        float w1 = wp[(k + 1) * N];
        float w2 = wp[(k + 2) * N];
        float w3 = wp[(k + 3) * N];
#pragma unroll
        for (int r = 0; r < ROWS; r++) {
            float4 x = *(const float4*)&xs[r][k];
            acc[r] = fmaf(x.x, w0, acc[r]);
            acc[r] = fmaf(x.y, w1, acc[r]);
            acc[r] = fmaf(x.z, w2, acc[r]);
            acc[r] = fmaf(x.w, w3, acc[r]);
        }
    }

    if (!DOLN) {
#pragma unroll
        for (int r = 0; r < ROWS; r++) out[(rowbase + r) * N + tid] = acc[r];
        return;
    }

#pragma unroll
    for (int r = 0; r < ROWS; r++) ob[r][tid] = acc[r];
    __syncthreads();

    const int wid = tid >> 5, lane = tid & 31;
    constexpr int NWARP = N / 32;
    constexpr int RPW = (ROWS + NWARP - 1) / NWARP;
#pragma unroll
    for (int rr = 0; rr < RPW; rr++) {
        int r = wid * RPW + rr;
        if (r < ROWS) {
            float s = 0.f, ss = 0.f;
#pragma unroll
            for (int j = lane; j < N; j += 32) { float v = ob[r][j]; s += v; ss = fmaf(v, v, ss); }
#pragma unroll
            for (int o = 16; o; o >>= 1) {
                s  += __shfl_xor_sync(0xffffffffu, s, o);
                ss += __shfl_xor_sync(0xffffffffu, ss, o);
            }
            float mean = s * (1.f / N);
            float var  = ss * (1.f / N) - mean * mean;
            float rstd = rsqrtf(var + 1e-5f);
#pragma unroll
            for (int j = lane; j < N; j += 32) {
                float v = (ob[r][j] - mean) * rstd * gamma[j] + beta[j];
                if (DORELU) v = fmaxf(v, 0.f);
                out[(rowbase + r) * N + j] = v;
            }
        }
    }
}

// ---------------------------------------------------------------------------
// Fused: vp = relu(LN(VF@v_W+v_b)); h = relu(LN(ppa + vp@a1_W_bot));
//        attn = sigmoid(h @ a2_W + a2_b).  vp/h never leave SMEM/regs.
// 16 view-rows per block, 256 threads.
// ---------------------------------------------------------------------------
__global__ void __launch_bounds__(256)
k3_vp_attn(const float* __restrict__ vf,
           const float* __restrict__ vW, const float* __restrict__ vb,
           const float* __restrict__ vg, const float* __restrict__ vbe,
           const float* __restrict__ a1Wb,          // a1_W + 256*256
           const float* __restrict__ ppa,           // includes a1_b
           const float* __restrict__ ag, const float* __restrict__ abe,
           const float* __restrict__ a2W, const float* __restrict__ a2b,
           float* __restrict__ attn)
{
    __shared__ float xs[16][256];
    __shared__ float ob[16][256];
    const int tid = threadIdx.x;
    const int wid = tid >> 5, lane = tid & 31;
    const size_t rowbase = (size_t)blockIdx.x * 16;

    // load 16 view-feature rows
    for (int idx = tid; idx < 16 * 64; idx += 256) {
        int r = idx >> 6, k4 = idx & 63;
        ((float4*)xs[r])[k4] = ((const float4*)(vf + (rowbase + r) * 256))[k4];
    }
    __syncthreads();

    float acc[16];
    // ---- GEMM 1: VF @ v_W -------------------------------------------------
    {
        float bv = vb[tid];
#pragma unroll
        for (int r = 0; r < 16; r++) acc[r] = bv;
    }
    {
        const float* wp = vW + tid;
        for (int k = 0; k < 256; k += 4) {
            float w0 = wp[(k + 0) * 256], w1 = wp[(k + 1) * 256];
            float w2 = wp[(k + 2) * 256], w3 = wp[(k + 3) * 256];
#pragma unroll
            for (int r = 0; r < 16; r++) {
                float4 x = *(const float4*)&xs[r][k];
                acc[r] = fmaf(x.x, w0, acc[r]);
                acc[r] = fmaf(x.y, w1, acc[r]);
                acc[r] = fmaf(x.z, w2, acc[r]);
                acc[r] = fmaf(x.w, w3, acc[r]);
            }
        }
    }
#pragma unroll
    for (int r = 0; r < 16; r++) ob[r][tid] = acc[r];
    __syncthreads();

    // ---- LN1 + ReLU -> normalized vp written back into xs ------------------
#pragma unroll
    for (int rr = 0; rr < 2; rr++) {
        int r = wid * 2 + rr;
        float s = 0.f, ss = 0.f;
#pragma unroll
        for (int j = lane; j < 256; j += 32) { float v = ob[r][j]; s += v; ss = fmaf(v, v, ss); }
#pragma unroll
        for (int o = 16; o; o >>= 1) {
            s  += __shfl_xor_sync(0xffffffffu, s, o);
            ss += __shfl_xor_sync(0xffffffffu, ss, o);
        }
        float mean = s * (1.f / 256.f);
        float rstd = rsqrtf(ss * (1.f / 256.f) - mean * mean + 1e-5f);
#pragma unroll
        for (int j = lane; j < 256; j += 32) {
            float v = (ob[r][j] - mean) * rstd * vg[j] + vbe[j];
            xs[r][j] = fmaxf(v, 0.f);
        }
    }
    __syncthreads();

    // ---- GEMM 2: vp @ a1_W_bot, init from ppa (pp @ a1_W_top + a1_b) ------
#pragma unroll
    for (int r = 0; r < 16; r++) {
        size_t gr = rowbase + r;                       // (b*M+m)*NP + p
        size_t pr = (gr >> 15) * (size_t)NPP + (gr & (NPP - 1));  // b*NP + p
        acc[r] = ppa[pr * 256 + tid];
    }
    {
        const float* wp = a1Wb + tid;
        for (int k = 0; k < 256; k += 4) {
            float w0 = wp[(k + 0) * 256], w1 = wp[(k + 1) * 256];
            float w2 = wp[(k + 2) * 256], w3 = wp[(k + 3) * 256];
#pragma unroll
            for (int r = 0; r < 16; r++) {
                float4 x = *(const float4*)&xs[r][k];
                acc[r] = fmaf(x.x, w0, acc[r]);
                acc[r] = fmaf(x.y, w1, acc[r]);
                acc[r] = fmaf(x.z, w2, acc[r]);
                acc[r] = fmaf(x.w, w3, acc[r]);
            }
        }
    }
    __syncthreads();   // xs reads done before ob overwritten? ob distinct; sync for ob reuse below
#pragma unroll
    for (int r = 0; r < 16; r++) ob[r][tid] = acc[r];
    __syncthreads();

    // ---- LN2 + ReLU + attention dot + sigmoid ------------------------------
#pragma unroll
    for (int rr = 0; rr < 2; rr++) {
        int r = wid * 2 + rr;
        float s = 0.f, ss = 0.f;
#pragma unroll
        for (int j = lane; j < 256; j += 32) { float v = ob[r][j]; s += v; ss = fmaf(v, v, ss); }
#pragma unroll
        for (int o = 16; o; o >>= 1) {
            s  += __shfl_xor_sync(0xffffffffu, s, o);
            ss += __shfl_xor_sync(0xffffffffu, ss, o);
        }
        float mean = s * (1.f / 256.f);
        float rstd = rsqrtf(ss * (1.f / 256.f) - mean * mean + 1e-5f);
        float ad = 0.f;
#pragma unroll
        for (int j = lane; j < 256; j += 32) {
            float v = fmaxf((ob[r][j] - mean) * rstd * ag[j] + abe[j], 0.f);
            ad = fmaf(v, a2W[j], ad);
        }
#pragma unroll
        for (int o = 16; o; o >>= 1) ad += __shfl_xor_sync(0xffffffffu, ad, o);
        if (lane == 0) {
            float logit = ad + a2b[0];
            attn[rowbase + r] = 1.f / (1.f + expf(-logit));
        }
    }
}

// ---------------------------------------------------------------------------
// Deterministic per-segment stats: one block per (b, superpoint).
// ---------------------------------------------------------------------------
__global__ void __launch_bounds__(256)
k4_segstats(const int* __restrict__ sp, const float* __restrict__ attn,
            const float* __restrict__ pp,
            float* __restrict__ segcnt, float* __restrict__ sega,
            float* __restrict__ segf)
{
    const int b = blockIdx.x >> 7;
    const int s = blockIdx.x & (SS - 1);
    const int tid = threadIdx.x, wid = tid >> 5, lane = tid & 31;

    __shared__ int sps[NPP];
    for (int i = tid; i < NPP / 4; i += 256)
        ((int4*)sps)[i] = ((const int4*)(sp + (size_t)b * NPP))[i];
    __syncthreads();

    float fsum[8];
#pragma unroll
    for (int j = 0; j < 8; j++) fsum[j] = 0.f;
    float asum = 0.f;
    int cnt = 0;

    // warp `wid` scans p in [wid*512, wid*512+512)
    for (int p0 = wid * 512; p0 < wid * 512 + 512; p0 += 32) {
        int pv = sps[p0 + lane];
        unsigned m = __ballot_sync(0xffffffffu, pv == s);
        while (m) {
            int bit = __ffs(m) - 1;
            m &= m - 1;
            int p = p0 + bit;
            cnt++;
            size_t row = ((size_t)b * NPP + p) * HH;
#pragma unroll
            for (int j = 0; j < 8; j++) fsum[j] += pp[row + lane + 32 * j];
            if (lane < MM) asum += attn[((size_t)(b * MM + lane)) * NPP + p];
        }
    }

    __shared__ float fpart[8][HH];
    __shared__ float apart[8][MM];
    __shared__ int   cpart[8];
#pragma unroll
    for (int j = 0; j < 8; j++) fpart[wid][lane + 32 * j] = fsum[j];
    if (lane < MM) apart[wid][lane] = asum;
    if (lane == 0) cpart[wid] = cnt;
    __syncthreads();

    const int seg = b * SS + s;
    {
        float t = 0.f;
#pragma unroll
        for (int w = 0; w < 8; w++) t += fpart[w][tid];
        segf[(size_t)seg * HH + tid] = t;
    }
    if (tid < MM) {
        float a = 0.f;
#pragma unroll
        for (int w = 0; w < 8; w++) a += apart[w][tid];
        sega[seg * MM + tid] = a;
    }
    if (tid == 0) {
        int c = 0;
#pragma unroll
        for (int w = 0; w < 8; w++) c += cpart[w];
        segcnt[seg] = (float)c;
    }
}

// ---------------------------------------------------------------------------
// Refine attention (cosine-sim segment smoothing) + softmax over views +
// weighted sum of view features.  One block per point.
// ---------------------------------------------------------------------------
__global__ void __launch_bounds__(256)
k5_refine(const int* __restrict__ sp, const float* __restrict__ pp,
          const float* __restrict__ attn,
          const float* __restrict__ segcnt, const float* __restrict__ sega,
          const float* __restrict__ segf,
          const float* __restrict__ vf, float* __restrict__ weighted)
{
    const int pr = blockIdx.x;
    const int b = pr >> 12, p = pr & (NPP - 1);
    const int tid = threadIdx.x, wid = tid >> 5, lane = tid & 31;

    const int s = sp[pr];
    const bool valid = (s >= 0);
    const int seg = valid ? b * SS + s : 0;

    float f = pp[(size_t)pr * HH + tid];
    float cnt = valid ? fmaxf(segcnt[seg], 1.f) : 1.f;
    float fm = valid ? segf[(size_t)seg * HH + tid] / cnt : 0.f;

    float d = f * fm, n1 = f * f, n2 = fm * fm;
#pragma unroll
    for (int o = 16; o; o >>= 1) {
        d  += __shfl_xor_sync(0xffffffffu, d, o);
        n1 += __shfl_xor_sync(0xffffffffu, n1, o);
        n2 += __shfl_xor_sync(0xffffffffu, n2, o);
    }
    __shared__ float r3[8][3];
    if (lane == 0) { r3[wid][0] = d; r3[wid][1] = n1; r3[wid][2] = n2; }
    __syncthreads();

    __shared__ float simsh;
    __shared__ float refv[MM];
    __shared__ float wgt[MM];
    if (tid == 0) {
        float D = 0.f, N1 = 0.f, N2 = 0.f;
#pragma unroll
        for (int w = 0; w < 8; w++) { D += r3[w][0]; N1 += r3[w][1]; N2 += r3[w][2]; }
        simsh = D / (fmaxf(sqrtf(N1), 1e-8f) * fmaxf(sqrtf(N2), 1e-8f));
    }
    __syncthreads();
    if (tid < MM) {
        float a = attn[((size_t)(b * MM + tid)) * NPP + p];
        float am = valid ? sega[seg * MM + tid] / cnt : 0.f;
        refv[tid] = valid ? am + (a - am) * simsh : a;
    }
    __syncthreads();
    if (tid == 0) {
        float mx = -1e30f;
#pragma unroll
        for (int m = 0; m < MM; m++) mx = fmaxf(mx, refv[m]);
        float se = 0.f;
        float e[MM];
#pragma unroll
        for (int m = 0; m < MM; m++) { e[m] = expf(refv[m] - mx); se += e[m]; }
        float inv = 1.f / se;
#pragma unroll
        for (int m = 0; m < MM; m++) wgt[m] = e[m] * inv;
    }
    __syncthreads();

    float acc = 0.f;
#pragma unroll
    for (int m = 0; m < MM; m++)
        acc = fmaf(wgt[m], vf[(((size_t)(b * MM + m)) * NPP + p) * HH + tid], acc);
    weighted[(size_t)pr * HH + tid] = acc;
}

// ---------------------------------------------------------------------------
// Launch
// ---------------------------------------------------------------------------
extern "C" void kernel_launch(void* const* d_in, const int* in_sizes, int n_in,
                              void* d_out, int out_size)
{
    const float* pf  = (const float*)d_in[0];
    const float* vf  = (const float*)d_in[1];
    const int*   sp  = (const int*)d_in[2];
    const float* pW  = (const float*)d_in[3];
    const float* pb  = (const float*)d_in[4];
    const float* pg  = (const float*)d_in[5];
    const float* pbe = (const float*)d_in[6];
    const float* vW  = (const float*)d_in[7];
    const float* vb  = (const float*)d_in[8];
    const float* vg  = (const float*)d_in[9];
    const float* vbe = (const float*)d_in[10];
    const float* a1W = (const float*)d_in[11];
    const float* a1b = (const float*)d_in[12];
    const float* ag  = (const float*)d_in[13];
    const float* abe = (const float*)d_in[14];
    const float* a2W = (const float*)d_in[15];
    const float* a2b = (const float*)d_in[16];
    const float* fW  = (const float*)d_in[17];
    const float* fb  = (const float*)d_in[18];
    const float* fg  = (const float*)d_in[19];
    const float* fbe = (const float*)d_in[20];

    float *pp, *ppa, *attn, *segcnt, *sega, *segf, *wtd, *wvp;
    cudaGetSymbolAddress((void**)&pp,     g_pp);
    cudaGetSymbolAddress((void**)&ppa,    g_ppa);
    cudaGetSymbolAddress((void**)&attn,   g_attn);
    cudaGetSymbolAddress((void**)&segcnt, g_segcnt);
    cudaGetSymbolAddress((void**)&sega,   g_sega);
    cudaGetSymbolAddress((void**)&segf,   g_segf);
    cudaGetSymbolAddress((void**)&wtd,    g_weighted);
    cudaGetSymbolAddress((void**)&wvp,    g_wvp);

    // 1. pp = relu(LN(PF @ p_W + p_b))
    rowgemm<16, 256, 256, true, true><<<NPTS / 16, 256>>>(
        pf, nullptr, pW, pb, pg, pbe, pp);

    // 2. ppa = pp @ a1_W[0:256] + a1_b      (broadcast half, no LN)
    rowgemm<16, 256, 256, false, false><<<NPTS / 16, 256>>>(
        pp, nullptr, a1W, a1b, nullptr, nullptr, ppa);

    // 3. fused vp GEMM + LN + h GEMM + LN + attention sigmoid
    k3_vp_attn<<<NVIEWS / 16, 256>>>(
        vf, vW, vb, vg, vbe, a1W + 256 * 256, ppa, ag, abe, a2W, a2b, attn);

    // 4. segment statistics (deterministic, no atomics)
    k4_segstats<<<BB * SS, 256>>>(sp, attn, pp, segcnt, sega, segf);

    // 5. refine + softmax over views + weighted view-feature sum
    k5_refine<<<NPTS, 256>>>(sp, pp, attn, segcnt, sega, segf, vf, wtd);

    // 6. wvp = relu(LN(weighted @ v_W + v_b))
    rowgemm<16, 256, 256, true, true><<<NPTS / 16, 256>>>(
        wtd, nullptr, vW, vb, vg, vbe, wvp);

    // 7. Z = LN([pp, wvp] @ f_W + f_b)   (no ReLU)  -> d_out
    rowgemm<8, 512, 512, true, false><<<NPTS / 8, 512>>>(
        pp, wvp, fW, fb, fg, fbe, (float*)d_out);
}

// round 2
// speedup vs baseline: 1.0086x; 1.0086x over previous
#include <cuda_runtime.h>
#include <math.h>

// Problem constants
#define BB   4
#define MM   8
#define NPP  4096
#define HH   256
#define FDD  512
#define SS   128

#define NPTS   (BB * NPP)        // 16384 point rows
#define NVIEWS (BB * MM * NPP)   // 131072 view rows

// ---------------------------------------------------------------------------
// Scratch (static device globals; no allocation allowed)
// ---------------------------------------------------------------------------
static __device__ float g_pp[NPTS * HH];        // relu(LN(PF@p_W))
static __device__ float g_ppa[NPTS * HH];       // pp @ a1_W_top + a1_b
static __device__ float g_attn[NVIEWS];         // sigmoid attention, [B,M,NP] order
static __device__ float g_segcnt[BB * SS];
static __device__ float g_sega[BB * SS * MM];
static __device__ float g_segf[BB * SS * HH];
static __device__ float g_weighted[NPTS * HH];  // softmax-weighted view feats
static __device__ float g_wvp[NPTS * HH];       // relu(LN(weighted@v_W))

// ---------------------------------------------------------------------------
// Generic fused row GEMM (+ optional concat-K input, + optional LN(+ReLU))
//   out[r, n] = act( LN_n( bias[n] + sum_k xs[r,k] * W[k*N+n] ) )
// One block computes ROWS full rows so LayerNorm is block-local.
// ---------------------------------------------------------------------------
template <int ROWS, int K, int N, bool DOLN, bool DORELU>
__global__ void __launch_bounds__(N)
rowgemm(const float* __restrict__ X, const float* __restrict__ X2,
        const float* __restrict__ W, const float* __restrict__ bias,
        const float* __restrict__ gamma, const float* __restrict__ beta,
        float* __restrict__ out)
{
    __shared__ float xs[ROWS][K];
    __shared__ float ob[DOLN ? ROWS : 1][N];

    const int tid = threadIdx.x;
    const size_t rowbase = (size_t)blockIdx.x * ROWS;
    constexpr int K4 = K / 4;
    constexpr int TOT4 = ROWS * K4;

    if (X2 == nullptr) {
        for (int idx = tid; idx < TOT4; idx += N) {
            int r = idx / K4, k4 = idx - r * K4;
            ((float4*)xs[r])[k4] =
                ((const float4*)(X + (rowbase + r) * K))[k4];
        }
    } else {
        constexpr int KH4 = K4 / 2;   // concat: first half from X, second from X2
        for (int idx = tid; idx < TOT4; idx += N) {
            int r = idx / K4, k4 = idx - r * K4;
            float4 v;
            if (k4 < KH4) v = ((const float4*)(X  + (rowbase + r) * (K / 2)))[k4];
            else          v = ((const float4*)(X2 + (rowbase + r) * (K / 2)))[k4 - KH4];
            ((float4*)xs[r])[k4] = v;
        }
    }
    __syncthreads();

    float acc[ROWS];
    {
        float bv = bias[tid];
#pragma unroll
        for (int r = 0; r < ROWS; r++) acc[r] = bv;
    }

    const float* wp = W + tid;
    for (int k = 0; k < K; k += 4) {
        float w0 = wp[(k + 0) * N];
        float w1 = wp[(k + 1) * N];
        float w2 = wp[(k + 2) * N];
        float w3 = wp[(k + 3) * N];
#pragma unroll
        for (int r = 0; r < ROWS; r++) {
            float4 x = *(const float4*)&xs[r][k];
            acc[r] = fmaf(x.x, w0, acc[r]);
            acc[r] = fmaf(x.y, w1, acc[r]);
            acc[r] = fmaf(x.z, w2, acc[r]);
            acc[r] = fmaf(x.w, w3, acc[r]);
        }
    }

    if (!DOLN) {
#pragma unroll
        for (int r = 0; r < ROWS; r++) out[(rowbase + r) * N + tid] = acc[r];
        return;
    }

#pragma unroll
    for (int r = 0; r < ROWS; r++) ob[r][tid] = acc[r];
    __syncthreads();

    const int wid = tid >> 5, lane = tid & 31;
    constexpr int NWARP = N / 32;
    constexpr int RPW = (ROWS + NWARP - 1) / NWARP;
#pragma unroll
    for (int rr = 0; rr < RPW; rr++) {
        int r = wid * RPW + rr;
        if (r < ROWS) {
            float s = 0.f, ss = 0.f;
#pragma unroll
            for (int j = lane; j < N; j += 32) { float v = ob[r][j]; s += v; ss = fmaf(v, v, ss); }
#pragma unroll
            for (int o = 16; o; o >>= 1) {
                s  += __shfl_xor_sync(0xffffffffu, s, o);
                ss += __shfl_xor_sync(0xffffffffu, ss, o);
            }
            float mean = s * (1.f / N);
            float var  = ss * (1.f / N) - mean * mean;
            float rstd = rsqrtf(var + 1e-5f);
#pragma unroll
            for (int j = lane; j < N; j += 32) {
                float v = (ob[r][j] - mean) * rstd * gamma[j] + beta[j];
                if (DORELU) v = fmaxf(v, 0.f);
                out[(rowbase + r) * N + j] = v;
            }
        }
    }
}

// ---------------------------------------------------------------------------
// Fused: vp = relu(LN(VF@v_W+v_b)); h = relu(LN(ppa + vp@a1_W_bot));
//        attn = sigmoid(h @ a2_W + a2_b).  vp/h never leave SMEM/regs.
// 16 view-rows per block, 256 threads.
// ---------------------------------------------------------------------------
__global__ void __launch_bounds__(256)
k3_vp_attn(const float* __restrict__ vf,
           const float* __restrict__ vW, const float* __restrict__ vb,
           const float* __restrict__ vg, const float* __restrict__ vbe,
           const float* __restrict__ a1Wb,          // a1_W + 256*256
           const float* __restrict__ ppa,           // includes a1_b
           const float* __restrict__ ag, const float* __restrict__ abe,
           const float* __restrict__ a2W, const float* __restrict__ a2b,
           float* __restrict__ attn)
{
    __shared__ float xs[16][256];
    __shared__ float ob[16][256];
    const int tid = threadIdx.x;
    const int wid = tid >> 5, lane = tid & 31;
    const size_t rowbase = (size_t)blockIdx.x * 16;

    // load 16 view-feature rows
    for (int idx = tid; idx < 16 * 64; idx += 256) {
        int r = idx >> 6, k4 = idx & 63;
        ((float4*)xs[r])[k4] = ((const float4*)(vf + (rowbase + r) * 256))[k4];
    }
    __syncthreads();

    float acc[16];
    // ---- GEMM 1: VF @ v_W -------------------------------------------------
    {
        float bv = vb[tid];
#pragma unroll
        for (int r = 0; r < 16; r++) acc[r] = bv;
    }
    {
        const float* wp = vW + tid;
        for (int k = 0; k < 256; k += 4) {
            float w0 = wp[(k + 0) * 256], w1 = wp[(k + 1) * 256];
            float w2 = wp[(k + 2) * 256], w3 = wp[(k + 3) * 256];
#pragma unroll
            for (int r = 0; r < 16; r++) {
                float4 x = *(const float4*)&xs[r][k];
                acc[r] = fmaf(x.x, w0, acc[r]);
                acc[r] = fmaf(x.y, w1, acc[r]);
                acc[r] = fmaf(x.z, w2, acc[r]);
                acc[r] = fmaf(x.w, w3, acc[r]);
            }
        }
    }
#pragma unroll
    for (int r = 0; r < 16; r++) ob[r][tid] = acc[r];
    __syncthreads();

    // ---- LN1 + ReLU -> normalized vp written back into xs ------------------
#pragma unroll
    for (int rr = 0; rr < 2; rr++) {
        int r = wid * 2 + rr;
        float s = 0.f, ss = 0.f;
#pragma unroll
        for (int j = lane; j < 256; j += 32) { float v = ob[r][j]; s += v; ss = fmaf(v, v, ss); }
#pragma unroll
        for (int o = 16; o; o >>= 1) {
            s  += __shfl_xor_sync(0xffffffffu, s, o);
            ss += __shfl_xor_sync(0xffffffffu, ss, o);
        }
        float mean = s * (1.f / 256.f);
        float rstd = rsqrtf(ss * (1.f / 256.f) - mean * mean + 1e-5f);
#pragma unroll
        for (int j = lane; j < 256; j += 32) {
            float v = (ob[r][j] - mean) * rstd * vg[j] + vbe[j];
            xs[r][j] = fmaxf(v, 0.f);
        }
    }
    __syncthreads();

    // ---- GEMM 2: vp @ a1_W_bot, init from ppa (pp @ a1_W_top + a1_b) ------
#pragma unroll
    for (int r = 0; r < 16; r++) {
        size_t gr = rowbase + r;                       // (b*M+m)*NP + p
        size_t pr = (gr >> 15) * (size_t)NPP + (gr & (NPP - 1));  // b*NP + p
        acc[r] = ppa[pr * 256 + tid];
    }
    {
        const float* wp = a1Wb + tid;
        for (int k = 0; k < 256; k += 4) {
            float w0 = wp[(k + 0) * 256], w1 = wp[(k + 1) * 256];
            float w2 = wp[(k + 2) * 256], w3 = wp[(k + 3) * 256];
#pragma unroll
            for (int r = 0; r < 16; r++) {
                float4 x = *(const float4*)&xs[r][k];
                acc[r] = fmaf(x.x, w0, acc[r]);
                acc[r] = fmaf(x.y, w1, acc[r]);
                acc[r] = fmaf(x.z, w2, acc[r]);
                acc[r] = fmaf(x.w, w3, acc[r]);
            }
        }
    }
    __syncthreads();   // xs reads done before ob overwritten? ob distinct; sync for ob reuse below
#pragma unroll
    for (int r = 0; r < 16; r++) ob[r][tid] = acc[r];
    __syncthreads();

    // ---- LN2 + ReLU + attention dot + sigmoid ------------------------------
#pragma unroll
    for (int rr = 0; rr < 2; rr++) {
        int r = wid * 2 + rr;
        float s = 0.f, ss = 0.f;
#pragma unroll
        for (int j = lane; j < 256; j += 32) { float v = ob[r][j]; s += v; ss = fmaf(v, v, ss); }
#pragma unroll
        for (int o = 16; o; o >>= 1) {
            s  += __shfl_xor_sync(0xffffffffu, s, o);
            ss += __shfl_xor_sync(0xffffffffu, ss, o);
        }
        float mean = s * (1.f / 256.f);
        float rstd = rsqrtf(ss * (1.f / 256.f) - mean * mean + 1e-5f);
        float ad = 0.f;
#pragma unroll
        for (int j = lane; j < 256; j += 32) {
            float v = fmaxf((ob[r][j] - mean) * rstd * ag[j] + abe[j], 0.f);
            ad = fmaf(v, a2W[j], ad);
        }
#pragma unroll
        for (int o = 16; o; o >>= 1) ad += __shfl_xor_sync(0xffffffffu, ad, o);
        if (lane == 0) {
            float logit = ad + a2b[0];
            attn[rowbase + r] = 1.f / (1.f + expf(-logit));
        }
    }
}

// ---------------------------------------------------------------------------
// Deterministic per-segment stats: one block per (b, superpoint).
// ---------------------------------------------------------------------------
__global__ void __launch_bounds__(256)
k4_segstats(const int* __restrict__ sp, const float* __restrict__ attn,
            const float* __restrict__ pp,
            float* __restrict__ segcnt, float* __restrict__ sega,
            float* __restrict__ segf)
{
    const int b = blockIdx.x >> 7;
    const int s = blockIdx.x & (SS - 1);
    const int tid = threadIdx.x, wid = tid >> 5, lane = tid & 31;

    __shared__ int sps[NPP];
    for (int i = tid; i < NPP / 4; i += 256)
        ((int4*)sps)[i] = ((const int4*)(sp + (size_t)b * NPP))[i];
    __syncthreads();

    float fsum[8];
#pragma unroll
    for (int j = 0; j < 8; j++) fsum[j] = 0.f;
    float asum = 0.f;
    int cnt = 0;

    // warp `wid` scans p in [wid*512, wid*512+512)
    for (int p0 = wid * 512; p0 < wid * 512 + 512; p0 += 32) {
        int pv = sps[p0 + lane];
        unsigned m = __ballot_sync(0xffffffffu, pv == s);
        while (m) {
            int bit = __ffs(m) - 1;
            m &= m - 1;
            int p = p0 + bit;
            cnt++;
            size_t row = ((size_t)b * NPP + p) * HH;
#pragma unroll
            for (int j = 0; j < 8; j++) fsum[j] += pp[row + lane + 32 * j];
            if (lane < MM) asum += attn[((size_t)(b * MM + lane)) * NPP + p];
        }
    }

    __shared__ float fpart[8][HH];
    __shared__ float apart[8][MM];
    __shared__ int   cpart[8];
#pragma unroll
    for (int j = 0; j < 8; j++) fpart[wid][lane + 32 * j] = fsum[j];
    if (lane < MM) apart[wid][lane] = asum;
    if (lane == 0) cpart[wid] = cnt;
    __syncthreads();

    const int seg = b * SS + s;
    {
        float t = 0.f;
#pragma unroll
        for (int w = 0; w < 8; w++) t += fpart[w][tid];
        segf[(size_t)seg * HH + tid] = t;
    }
    if (tid < MM) {
        float a = 0.f;
#pragma unroll
        for (int w = 0; w < 8; w++) a += apart[w][tid];
        sega[seg * MM + tid] = a;
    }
    if (tid == 0) {
        int c = 0;
#pragma unroll
        for (int w = 0; w < 8; w++) c += cpart[w];
        segcnt[seg] = (float)c;
    }
}

// ---------------------------------------------------------------------------
// Refine attention (cosine-sim segment smoothing) + softmax over views +
// weighted sum of view features.  One block per point.
// ---------------------------------------------------------------------------
__global__ void __launch_bounds__(256)
k5_refine(const int* __restrict__ sp, const float* __restrict__ pp,
          const float* __restrict__ attn,
          const float* __restrict__ segcnt, const float* __restrict__ sega,
          const float* __restrict__ segf,
          const float* __restrict__ vf, float* __restrict__ weighted)
{
    const int pr = blockIdx.x;
    const int b = pr >> 12, p = pr & (NPP - 1);
    const int tid = threadIdx.x, wid = tid >> 5, lane = tid & 31;

    const int s = sp[pr];
    const bool valid = (s >= 0);
    const int seg = valid ? b * SS + s : 0;

    float f = pp[(size_t)pr * HH + tid];
    float cnt = valid ? fmaxf(segcnt[seg], 1.f) : 1.f;
    float fm = valid ? segf[(size_t)seg * HH + tid] / cnt : 0.f;

    float d = f * fm, n1 = f * f, n2 = fm * fm;
#pragma unroll
    for (int o = 16; o; o >>= 1) {
        d  += __shfl_xor_sync(0xffffffffu, d, o);
        n1 += __shfl_xor_sync(0xffffffffu, n1, o);
        n2 += __shfl_xor_sync(0xffffffffu, n2, o);
    }
    __shared__ float r3[8][3];
    if (lane == 0) { r3[wid][0] = d; r3[wid][1] = n1; r3[wid][2] = n2; }
    __syncthreads();

    __shared__ float simsh;
    __shared__ float refv[MM];
    __shared__ float wgt[MM];
    if (tid == 0) {
        float D = 0.f, N1 = 0.f, N2 = 0.f;
#pragma unroll
        for (int w = 0; w < 8; w++) { D += r3[w][0]; N1 += r3[w][1]; N2 += r3[w][2]; }
        simsh = D / (fmaxf(sqrtf(N1), 1e-8f) * fmaxf(sqrtf(N2), 1e-8f));
    }
    __syncthreads();
    if (tid < MM) {
        float a = attn[((size_t)(b * MM + tid)) * NPP + p];
        float am = valid ? sega[seg * MM + tid] / cnt : 0.f;
        refv[tid] = valid ? am + (a - am) * simsh : a;
    }
    __syncthreads();
    if (tid == 0) {
        float mx = -1e30f;
#pragma unroll
        for (int m = 0; m < MM; m++) mx = fmaxf(mx, refv[m]);
        float se = 0.f;
        float e[MM];
#pragma unroll
        for (int m = 0; m < MM; m++) { e[m] = expf(refv[m] - mx); se += e[m]; }
        float inv = 1.f / se;
#pragma unroll
        for (int m = 0; m < MM; m++) wgt[m] = e[m] * inv;
    }
    __syncthreads();

    float acc = 0.f;
#pragma unroll
    for (int m = 0; m < MM; m++)
        acc = fmaf(wgt[m], vf[(((size_t)(b * MM + m)) * NPP + p) * HH + tid], acc);
    weighted[(size_t)pr * HH + tid] = acc;
}

// ---------------------------------------------------------------------------
// Launch
// ---------------------------------------------------------------------------
extern "C" void kernel_launch(void* const* d_in, const int* in_sizes, int n_in,
                              void* d_out, int out_size)
{
    const float* pf  = (const float*)d_in[0];
    const float* vf  = (const float*)d_in[1];
    const int*   sp  = (const int*)d_in[2];
    const float* pW  = (const float*)d_in[3];
    const float* pb  = (const float*)d_in[4];
    const float* pg  = (const float*)d_in[5];
    const float* pbe = (const float*)d_in[6];
    const float* vW  = (const float*)d_in[7];
    const float* vb  = (const float*)d_in[8];
    const float* vg  = (const float*)d_in[9];
    const float* vbe = (const float*)d_in[10];
    const float* a1W = (const float*)d_in[11];
    const float* a1b = (const float*)d_in[12];
    const float* ag  = (const float*)d_in[13];
    const float* abe = (const float*)d_in[14];
    const float* a2W = (const float*)d_in[15];
    const float* a2b = (const float*)d_in[16];
    const float* fW  = (const float*)d_in[17];
    const float* fb  = (const float*)d_in[18];
    const float* fg  = (const float*)d_in[19];
    const float* fbe = (const float*)d_in[20];

    float *pp, *ppa, *attn, *segcnt, *sega, *segf, *wtd, *wvp;
    cudaGetSymbolAddress((void**)&pp,     g_pp);
    cudaGetSymbolAddress((void**)&ppa,    g_ppa);
    cudaGetSymbolAddress((void**)&attn,   g_attn);
    cudaGetSymbolAddress((void**)&segcnt, g_segcnt);
    cudaGetSymbolAddress((void**)&sega,   g_sega);
    cudaGetSymbolAddress((void**)&segf,   g_segf);
    cudaGetSymbolAddress((void**)&wtd,    g_weighted);
    cudaGetSymbolAddress((void**)&wvp,    g_wvp);

    // 1. pp = relu(LN(PF @ p_W + p_b))
    rowgemm<16, 256, 256, true, true><<<NPTS / 16, 256>>>(
        pf, nullptr, pW, pb, pg, pbe, pp);

    // 2. ppa = pp @ a1_W[0:256] + a1_b      (broadcast half, no LN)
    rowgemm<16, 256, 256, false, false><<<NPTS / 16, 256>>>(
        pp, nullptr, a1W, a1b, nullptr, nullptr, ppa);

    // 3. fused vp GEMM + LN + h GEMM + LN + attention sigmoid
    k3_vp_attn<<<NVIEWS / 16, 256>>>(
        vf, vW, vb, vg, vbe, a1W + 256 * 256, ppa, ag, abe, a2W, a2b, attn);

    // 4. segment statistics (deterministic, no atomics)
    k4_segstats<<<BB * SS, 256>>>(sp, attn, pp, segcnt, sega, segf);

    // 5. refine + softmax over views + weighted view-feature sum
    k5_refine<<<NPTS, 256>>>(sp, pp, attn, segcnt, sega, segf, vf, wtd);

    // 6. wvp = relu(LN(weighted @ v_W + v_b))
    rowgemm<16, 256, 256, true, true><<<NPTS / 16, 256>>>(
        wtd, nullptr, vW, vb, vg, vbe, wvp);

    // 7. Z = LN([pp, wvp] @ f_W + f_b)   (no ReLU)  -> d_out
    rowgemm<8, 512, 512, true, false><<<NPTS / 8, 512>>>(
        pp, wvp, fW, fb, fg, fbe, (float*)d_out);
}